// round 15
// baseline (speedup 1.0000x reference)
#include <cuda_runtime.h>

// GlobalFeatureBlock_Diffusion — fully fused single kernel.
// One CTA per (b,h) row: 4 depthwise 3x3 convs + BN + ReLU, coefficient
// precompute, K=2 diffusion steps (W rolls mod 128, C rolls mod 64),
// final BN + ReLU, all in shared memory.
// R14: 1024 threads/CTA (WPT=8) to raise occupancy 25% -> 50%.

#define DTc 0.2f
#define EPSc 1e-3f

constexpr int Cc   = 64;
constexpr int Wc   = 128;
constexpr int SROW = 130 * 64;            // padded row stride (floats)
constexpr int CB   = 3 * SROW;            // conv-buffer base (floats)
constexpr int NTHR = 1024;
constexpr int WPT  = 8;                   // w-positions per thread
constexpr int SMEM_FLOATS = CB + 4 * Wc * Cc;   // 24960 + 32768 = 57728
constexpr int SMEM_BYTES  = SMEM_FLOATS * 4;    // 230912 B

__global__ __launch_bounds__(NTHR, 1)
void gfb_diffusion_kernel(const float* __restrict__ s0,
                          const float* __restrict__ kg,  const float* __restrict__ kg1,
                          const float* __restrict__ kDx, const float* __restrict__ kDy,
                          const float* __restrict__ bng, const float* __restrict__ bng1,
                          const float* __restrict__ bnDx,const float* __restrict__ bnDy,
                          const float* __restrict__ bn_out,
                          float* __restrict__ out)
{
    extern __shared__ float sm[];
    const int tid = threadIdx.x;
    const int c   = tid & 63;          // channel owned by this thread
    const int wg  = tid >> 6;          // 16 groups of 64 threads
    const int w0  = wg * WPT;
    const int bh  = blockIdx.x;        // b*128 + h
    const int h   = bh & 127;

    // ---------------- Phase 0: load 3 rows of s0 (zero-padded cols 0 & 129) ----
    #pragma unroll
    for (int r = 0; r < 3; ++r) {
        float* dst = sm + r * SROW;
        if (tid < 64) { dst[tid] = 0.f; dst[129 * 64 + tid] = 0.f; }
        const int hh = h + r - 1;
        float4* d4 = (float4*)(dst + 64);
        if (hh >= 0 && hh < 128) {
            const float4* src = (const float4*)(s0 + (size_t)(bh + (r - 1)) * (Wc * Cc));
            #pragma unroll
            for (int k = 0; k < 2; ++k) d4[tid + k * NTHR] = src[tid + k * NTHR];
        } else {
            const float4 z = make_float4(0.f, 0.f, 0.f, 0.f);
            #pragma unroll
            for (int k = 0; k < 2; ++k) d4[tid + k * NTHR] = z;
        }
    }

    // ---------------- per-thread conv weights with BN scale folded in ----------
    float wreg[4][9], bias[4];
    {
        const float* ks[4]  = {kg, kg1, kDx, kDy};
        const float* bns[4] = {bng, bng1, bnDx, bnDy};
        #pragma unroll
        for (int j = 0; j < 4; ++j) {
            const float gamma = bns[j][c];
            const float beta  = bns[j][64 + c];
            const float mean  = bns[j][128 + c];
            const float var   = bns[j][192 + c];
            const float sc    = gamma / sqrtf(var + EPSc);
            bias[j] = beta - mean * sc;
            #pragma unroll
            for (int t = 0; t < 9; ++t) wreg[j][t] = ks[j][t * 64 + c] * sc;
        }
    }
    float sc_o, b_o;
    {
        const float gamma = bn_out[c], beta = bn_out[64 + c];
        const float mean  = bn_out[128 + c], var = bn_out[192 + c];
        sc_o = gamma / sqrtf(var + EPSc);
        b_o  = beta - mean * sc_o;
    }

    __syncthreads();

    float* g0  = sm + CB;               // g   (later: Wm)
    float* g1b = sm + CB + 8192;        // g1  (later: Cm)
    float* dxb = sm + CB + 16384;       // Dx  (later: Wp)
    float* dyb = sm + CB + 24576;       // Dy  (later: Cp)

    // ---------------- Phase 1: depthwise 3x3 conv + BN + ReLU (x4) -------------
    {
        // sliding 3x3 window over padded columns; output w uses padded cols w,w+1,w+2
        float a0 = sm[0 * SROW + (w0)     * 64 + c], a1 = sm[0 * SROW + (w0 + 1) * 64 + c];
        float m0 = sm[1 * SROW + (w0)     * 64 + c], m1 = sm[1 * SROW + (w0 + 1) * 64 + c];
        float z0 = sm[2 * SROW + (w0)     * 64 + c], z1 = sm[2 * SROW + (w0 + 1) * 64 + c];
        #pragma unroll
        for (int i = 0; i < WPT; ++i) {
            const int w = w0 + i;
            const float a2 = sm[0 * SROW + (w + 2) * 64 + c];
            const float m2 = sm[1 * SROW + (w + 2) * 64 + c];
            const float z2 = sm[2 * SROW + (w + 2) * 64 + c];
            #pragma unroll
            for (int j = 0; j < 4; ++j) {
                float acc = bias[j];
                acc = fmaf(a0, wreg[j][0], acc);
                acc = fmaf(a1, wreg[j][1], acc);
                acc = fmaf(a2, wreg[j][2], acc);
                acc = fmaf(m0, wreg[j][3], acc);
                acc = fmaf(m1, wreg[j][4], acc);
                acc = fmaf(m2, wreg[j][5], acc);
                acc = fmaf(z0, wreg[j][6], acc);
                acc = fmaf(z1, wreg[j][7], acc);
                acc = fmaf(z2, wreg[j][8], acc);
                acc = fmaxf(acc, 0.f);
                float* buf = (j == 0) ? g0 : (j == 1) ? g1b : (j == 2) ? dxb : dyb;
                buf[w * 64 + c] = acc;
            }
            a0 = a1; a1 = a2;
            m0 = m1; m1 = m2;
            z0 = z1; z1 = z2;
        }
    }
    __syncthreads();

    // ---------------- Phase 2 (B1): Ch (needs cross-thread raw g/g1) + cf ------
    float cfreg[WPT];
    float* chb = sm + 2 * SROW;                 // row2 region reused: Ch buffer
    const int cm = (c + 63) & 63, cp = (c + 1) & 63;
    #pragma unroll
    for (int i = 0; i < WPT; ++i) {
        const int w  = w0 + i;
        const int wm = (w + 127) & 127, wp = (w + 1) & 127;
        const float Dxv = dxb[w * 64 + c], Dyv = dyb[w * 64 + c];
        const float Bx2 = 2.f * DTc * Dxv, By2 = 2.f * DTc * Dyv;
        const float Dv  = __fdividef(1.f, 1.f + Bx2 + By2);
        // -2E = -DT * sd ; sd = (g[w-1]-g[w+1]) + (g1[c-1]-g1[c+1])
        const float sd  = (g0[wm * 64 + c] - g0[wp * 64 + c])
                        + (g1b[w * 64 + cm] - g1b[w * 64 + cp]);
        chb[w * 64 + c] = -DTc * sd * Dv;
        // h0 == f for both K=2 steps: cf = D*((1-2Bx-2By) + 2*DT)
        cfreg[i] = Dv * (1.f - Bx2 - By2 + 2.f * DTc);
    }
    __syncthreads();

    // ---------------- Phase 3 (B2 + iter1): coeffs in place, first step --------
    float h1reg[WPT];
    float* h1b = sm;                    // row0 region reused: h1 buffer [w*64+c]
    const float* f = sm + SROW;         // padded row1 = f
    #pragma unroll
    for (int i = 0; i < WPT; ++i) {
        const int w   = w0 + i;
        const int idx = w * 64 + c;
        const int wm  = (w + 127) & 127, wp = (w + 1) & 127;
        const float gv = g0[idx], g1v = g1b[idx], Dxv = dxb[idx], Dyv = dyb[idx];
        const float Bx2 = 2.f * DTc * Dxv, By2 = 2.f * DTc * Dyv;
        const float Dv  = __fdividef(1.f, 1.f + Bx2 + By2);
        const float Wm = Dv * (Bx2 - DTc * gv);   // (-Ax+2Bx)*D  -> h[w-1]
        const float Wp = Dv * (Bx2 + DTc * gv);   // ( Ax+2Bx)*D  -> h[w+1]
        const float Cm = Dv * (By2 - DTc * g1v);  // (-Ay+2By)*D  -> h[c-1]
        const float Cp = Dv * (By2 + DTc * g1v);  // ( Ay+2By)*D  -> h[c+1]
        g0[idx] = Wm; dxb[idx] = Wp; g1b[idx] = Cm; dyb[idx] = Cp;   // in place
        const float Chv = chb[idx];
        const float fc  = f[(w + 1) * 64 + c];
        const float fwm = f[(wm + 1) * 64 + c];
        const float fwp = f[(wp + 1) * 64 + c];
        const float fcm = f[(w + 1) * 64 + cm];
        const float fcp = f[(w + 1) * 64 + cp];
        // iter1: h == h0 == f  ->  (cf + Ch) * f + neighbor terms on f
        const float h1 = (cfreg[i] + Chv) * fc
                       + Wm * fwm + Wp * fwp + Cm * fcm + Cp * fcp;
        h1b[idx]  = h1;
        h1reg[i]  = h1;
    }
    __syncthreads();

    // ---------------- Phase 4 (iter2) + output BN + ReLU -----------------------
    #pragma unroll
    for (int i = 0; i < WPT; ++i) {
        const int w   = w0 + i;
        const int idx = w * 64 + c;
        const int wm  = (w + 127) & 127, wp = (w + 1) & 127;
        const float Wm = g0[idx], Wp = dxb[idx], Cm = g1b[idx], Cp = dyb[idx];
        const float Chv = chb[idx];
        const float hm  = (i == 0)       ? h1b[wm * 64 + c] : h1reg[i - 1];
        const float hp  = (i == WPT - 1) ? h1b[wp * 64 + c] : h1reg[i + 1];
        const float hcm = h1b[w * 64 + cm];
        const float hcp = h1b[w * 64 + cp];
        const float fc  = f[(w + 1) * 64 + c];
        const float h2 = cfreg[i] * fc + Chv * h1reg[i]
                       + Wm * hm + Wp * hp + Cm * hcm + Cp * hcp;
        const float o = fmaf(sc_o, h2, b_o);
        out[(size_t)bh * (Wc * Cc) + idx] = fmaxf(o, 0.f);
    }
}

extern "C" void kernel_launch(void* const* d_in, const int* in_sizes, int n_in,
                              void* d_out, int out_size)
{
    (void)in_sizes; (void)n_in; (void)out_size;
    const float* s0     = (const float*)d_in[0];
    const float* kg     = (const float*)d_in[1];
    const float* kg1    = (const float*)d_in[2];
    const float* kDx    = (const float*)d_in[3];
    const float* kDy    = (const float*)d_in[4];
    const float* bng    = (const float*)d_in[5];
    const float* bng1   = (const float*)d_in[6];
    const float* bnDx   = (const float*)d_in[7];
    const float* bnDy   = (const float*)d_in[8];
    const float* bn_out = (const float*)d_in[9];
    float* out = (float*)d_out;

    cudaFuncSetAttribute(gfb_diffusion_kernel,
                         cudaFuncAttributeMaxDynamicSharedMemorySize, SMEM_BYTES);

    // one CTA per (b,h) row: 16 * 128 = 2048 CTAs
    gfb_diffusion_kernel<<<2048, NTHR, SMEM_BYTES>>>(
        s0, kg, kg1, kDx, kDy, bng, bng1, bnDx, bnDy, bn_out, out);
}

// round 16
// speedup vs baseline: 1.1501x; 1.1501x over previous
#include <cuda_runtime.h>

// GlobalFeatureBlock_Diffusion — fully fused, one CTA per (b,h) row.
// R15: coefficients live in registers (no smem round-trip), channel-neighbor
// access via warp shuffles, 3 barriers, smem traffic ~halved.

#define DTc 0.2f
#define EPSc 1e-3f

constexpr int Cc   = 64;
constexpr int Wc   = 128;
constexpr int SROW = 130 * 64;            // padded row stride (floats)
constexpr int NTHR = 512;
constexpr int WPT  = 16;                  // w-positions per thread
// layout: row0 [0,8320) (reused as h1), row1=f [8320,16640), row2 [16640,24960)
//         B1=g [24960,+8192), B2=g1, B3=Wm, B4=Wp
constexpr int B1o = 3 * SROW;
constexpr int SMEM_FLOATS = B1o + 4 * Wc * Cc;   // 57728
constexpr int SMEM_BYTES  = SMEM_FLOATS * 4;     // 230912 B

__global__ __launch_bounds__(NTHR, 1)
void gfb_diffusion_kernel(const float* __restrict__ s0,
                          const float* __restrict__ kg,  const float* __restrict__ kg1,
                          const float* __restrict__ kDx, const float* __restrict__ kDy,
                          const float* __restrict__ bng, const float* __restrict__ bng1,
                          const float* __restrict__ bnDx,const float* __restrict__ bnDy,
                          const float* __restrict__ bn_out,
                          float* __restrict__ out)
{
    extern __shared__ float sm[];
    const int tid  = threadIdx.x;
    const int c    = tid & 63;         // channel owned by this thread
    const int lane = tid & 31;
    const int wg   = tid >> 6;         // 8 groups of 64 threads
    const int w0   = wg * WPT;
    const int bh   = blockIdx.x;       // b*128 + h
    const int h    = bh & 127;
    const int cm   = (c + 63) & 63, cp = (c + 1) & 63;

    float* const f1  = sm + SROW;      // padded middle row (= f), stays live
    float* const g0  = sm + B1o;            // g
    float* const g1b = sm + B1o + 8192;     // g1
    float* const wmb = sm + B1o + 16384;    // Wm
    float* const wpb = sm + B1o + 24576;    // Wp
    float* const h1b = sm;                  // h1 (row0 region, dead after conv)

    // ---------------- Phase 0: load 3 rows of s0 (zero-padded cols 0 & 129) ----
    #pragma unroll
    for (int r = 0; r < 3; ++r) {
        float* dst = sm + r * SROW;
        if (tid < 64) { dst[tid] = 0.f; dst[129 * 64 + tid] = 0.f; }
        const int hh = h + r - 1;
        float4* d4 = (float4*)(dst + 64);
        if (hh >= 0 && hh < 128) {
            const float4* src = (const float4*)(s0 + (size_t)(bh + (r - 1)) * (Wc * Cc));
            #pragma unroll
            for (int k = 0; k < 4; ++k) d4[tid + k * NTHR] = src[tid + k * NTHR];
        } else {
            const float4 z = make_float4(0.f, 0.f, 0.f, 0.f);
            #pragma unroll
            for (int k = 0; k < 4; ++k) d4[tid + k * NTHR] = z;
        }
    }

    // ---------------- per-thread conv weights with BN scale folded in ----------
    float wreg[4][9], bias[4];
    {
        const float* ks[4]  = {kg, kg1, kDx, kDy};
        const float* bns[4] = {bng, bng1, bnDx, bnDy};
        #pragma unroll
        for (int j = 0; j < 4; ++j) {
            const float gamma = bns[j][c];
            const float beta  = bns[j][64 + c];
            const float mean  = bns[j][128 + c];
            const float var   = bns[j][192 + c];
            const float sc    = gamma / sqrtf(var + EPSc);
            bias[j] = beta - mean * sc;
            #pragma unroll
            for (int t = 0; t < 9; ++t) wreg[j][t] = ks[j][t * 64 + c] * sc;
        }
    }
    float sc_o, b_o;
    {
        const float gamma = bn_out[c], beta = bn_out[64 + c];
        const float mean  = bn_out[128 + c], var = bn_out[192 + c];
        sc_o = gamma / sqrtf(var + EPSc);
        b_o  = beta - mean * sc_o;
    }

    __syncthreads();

    // ---------------- Phase 1: conv + BN + ReLU + coefficient fold -------------
    // keeps cf, Cm, Cp in registers; stores g, g1, Wm, Wp to smem
    float cf[WPT], Cmr[WPT], Cpr[WPT];
    {
        float a0 = sm[0 * SROW + (w0)     * 64 + c], a1 = sm[0 * SROW + (w0 + 1) * 64 + c];
        float m0 = sm[1 * SROW + (w0)     * 64 + c], m1 = sm[1 * SROW + (w0 + 1) * 64 + c];
        float z0 = sm[2 * SROW + (w0)     * 64 + c], z1 = sm[2 * SROW + (w0 + 1) * 64 + c];
        #pragma unroll
        for (int i = 0; i < WPT; ++i) {
            const int w = w0 + i;
            const float a2 = sm[0 * SROW + (w + 2) * 64 + c];
            const float m2 = sm[1 * SROW + (w + 2) * 64 + c];
            const float z2 = sm[2 * SROW + (w + 2) * 64 + c];
            float acc[4];
            #pragma unroll
            for (int j = 0; j < 4; ++j) {
                float a = bias[j];
                a = fmaf(a0, wreg[j][0], a);
                a = fmaf(a1, wreg[j][1], a);
                a = fmaf(a2, wreg[j][2], a);
                a = fmaf(m0, wreg[j][3], a);
                a = fmaf(m1, wreg[j][4], a);
                a = fmaf(m2, wreg[j][5], a);
                a = fmaf(z0, wreg[j][6], a);
                a = fmaf(z1, wreg[j][7], a);
                a = fmaf(z2, wreg[j][8], a);
                acc[j] = fmaxf(a, 0.f);
            }
            const float gv = acc[0], g1v = acc[1];
            const float Bx2 = 2.f * DTc * acc[2];     // 2*DT*Dx
            const float By2 = 2.f * DTc * acc[3];     // 2*DT*Dy
            const float Dv  = __fdividef(1.f, 1.f + Bx2 + By2);
            const int idx = w * 64 + c;
            cf[i]  = Dv * (1.f + 2.f * DTc - Bx2 - By2);
            Cmr[i] = Dv * (By2 - DTc * g1v);
            Cpr[i] = Dv * (By2 + DTc * g1v);
            g0[idx]  = gv;
            g1b[idx] = g1v;
            wmb[idx] = Dv * (Bx2 - DTc * gv);
            wpb[idx] = Dv * (Bx2 + DTc * gv);
            a0 = a1; a1 = a2;
            m0 = m1; m1 = m2;
            z0 = z1; z1 = z2;
        }
    }
    __syncthreads();

    // ---------------- Phase A: Ch + diffusion iter 1 ---------------------------
    float Chr[WPT], h1reg[WPT];
    {
        // sliding f with wrap (rolls use mod-128, not zero padding)
        float fmv = f1[(((w0 + 127) & 127) + 1) * 64 + c];
        float fcv = f1[(w0 + 1) * 64 + c];
        #pragma unroll
        for (int i = 0; i < WPT; ++i) {
            const int w   = w0 + i;
            const int idx = w * 64 + c;
            const int wm  = (w + 127) & 127, wp = (w + 1) & 127;
            const float fpv = f1[(wp + 1) * 64 + c];

            const float Dv = (cf[i] + 1.f) * (1.f / (1.f + 2.f * DTc + 1.f)); // (cf+1)/2.4
            const float sd = (g0[wm * 64 + c] - g0[wp * 64 + c])
                           + (g1b[w * 64 + cm] - g1b[w * 64 + cp]);
            const float Chv = -DTc * sd * Dv;
            Chr[i] = Chv;

            float fcm = __shfl_up_sync(0xffffffffu, fcv, 1);
            if (lane == 0)  fcm = f1[(w + 1) * 64 + cm];
            float fcp = __shfl_down_sync(0xffffffffu, fcv, 1);
            if (lane == 31) fcp = f1[(w + 1) * 64 + cp];

            const float Wm = wmb[idx], Wp = wpb[idx];
            // iter1: h == h0 == f
            const float h1 = (cf[i] + Chv) * fcv
                           + Wm * fmv + Wp * fpv + Cmr[i] * fcm + Cpr[i] * fcp;
            h1reg[i]  = h1;
            h1b[idx]  = h1;

            fmv = fcv; fcv = fpv;
        }
    }
    __syncthreads();

    // ---------------- Phase B: diffusion iter 2 + output BN + ReLU -------------
    #pragma unroll
    for (int i = 0; i < WPT; ++i) {
        const int w   = w0 + i;
        const int idx = w * 64 + c;
        const int wm  = (w + 127) & 127, wp = (w + 1) & 127;

        const float hc  = h1reg[i];
        const float hm  = (i == 0)       ? h1b[wm * 64 + c] : h1reg[i - 1];
        const float hp  = (i == WPT - 1) ? h1b[wp * 64 + c] : h1reg[i + 1];
        float hcm = __shfl_up_sync(0xffffffffu, hc, 1);
        if (lane == 0)  hcm = h1b[w * 64 + cm];
        float hcp = __shfl_down_sync(0xffffffffu, hc, 1);
        if (lane == 31) hcp = h1b[w * 64 + cp];

        const float fcv = f1[(w + 1) * 64 + c];
        const float Wm = wmb[idx], Wp = wpb[idx];
        const float h2 = cf[i] * fcv + Chr[i] * hc
                       + Wm * hm + Wp * hp + Cmr[i] * hcm + Cpr[i] * hcp;
        const float o = fmaf(sc_o, h2, b_o);
        out[(size_t)bh * (Wc * Cc) + idx] = fmaxf(o, 0.f);
    }
}

extern "C" void kernel_launch(void* const* d_in, const int* in_sizes, int n_in,
                              void* d_out, int out_size)
{
    (void)in_sizes; (void)n_in; (void)out_size;
    const float* s0     = (const float*)d_in[0];
    const float* kg     = (const float*)d_in[1];
    const float* kg1    = (const float*)d_in[2];
    const float* kDx    = (const float*)d_in[3];
    const float* kDy    = (const float*)d_in[4];
    const float* bng    = (const float*)d_in[5];
    const float* bng1   = (const float*)d_in[6];
    const float* bnDx   = (const float*)d_in[7];
    const float* bnDy   = (const float*)d_in[8];
    const float* bn_out = (const float*)d_in[9];
    float* out = (float*)d_out;

    cudaFuncSetAttribute(gfb_diffusion_kernel,
                         cudaFuncAttributeMaxDynamicSharedMemorySize, SMEM_BYTES);

    // one CTA per (b,h) row: 16 * 128 = 2048 CTAs
    gfb_diffusion_kernel<<<2048, NTHR, SMEM_BYTES>>>(
        s0, kg, kg1, kDx, kDy, bng, bng1, bnDx, bnDy, bn_out, out);
}